// round 10
// baseline (speedup 1.0000x reference)
#include <cuda_runtime.h>

// PositionalEncoding: out[b,t,i] = x[b,t,i] + P[t,i]
//   P[2f,   i] = sin(f / 10000^(2i/F))
//   P[2f+1, i] = cos(f / 10000^(2i/F))
// x: [32, 2048, 1024] fp32. HBM-streaming-bound (512MB floor).
// R9 = R7 champion (256 thr, occ cap 4, float4, BY=2, software-pipelined
// loads ahead of the sin/cos chain) + ONE knob: streaming stores (__stcs)
// so the once-written output stream is evict-first in L2, leaving more
// LTS capacity/bandwidth for the load stream. Loads stay default-cached
// (both .cg and .cs loads regressed in earlier rounds).

#define PE_T 2048
#define PE_F 1024
#define PE_B 32
#define PE_BY 2                      // batch split factor
#define PE_BPER (PE_B / PE_BY)       // 16 batches per thread
#define PE_H (PE_BPER / 2)           // 8 per pipeline half

__global__ __launch_bounds__(256, 4)
void pe_add_kernel(const float* __restrict__ x, float* __restrict__ out) {
    const int t = blockIdx.x;          // row 0..2047
    const int c = threadIdx.x;         // float4 column 0..255
    const int b0 = blockIdx.y * PE_BPER;

    const float4* __restrict__ x4 = (const float4*)x;
    float4* __restrict__ o4 = (float4*)out;
    const size_t row_stride4 = (size_t)PE_T * (PE_F / 4);   // float4 per batch slice
    const size_t base = (size_t)t * (PE_F / 4) + (size_t)c
                      + (size_t)b0 * row_stride4;

    // ---- Pipeline stage 1: issue first 8 loads (independent of P) ----
    float4 buf[PE_H];
#pragma unroll
    for (int b = 0; b < PE_H; b++)
        buf[b] = x4[base + (size_t)b * row_stride4];

    // ---- Compute P while loads are in flight ----
    const float f = (float)(t >> 1);
    const bool is_sin = (t & 1) == 0;
    float pv[4];
#pragma unroll
    for (int k = 0; k < 4; k++) {
        const int i = c * 4 + k;
        const float e = (float)i * (1.0f / 512.0f);   // 2*i/F, exact in fp32
        const float den = powf(10000.0f, e);
        const float ang = f / den;
        pv[k] = is_sin ? sinf(ang) : cosf(ang);
    }
    const float4 p = make_float4(pv[0], pv[1], pv[2], pv[3]);

    // ---- Stage 2: issue second-half loads, then drain first half ----
    float4 buf2[PE_H];
#pragma unroll
    for (int b = 0; b < PE_H; b++)
        buf2[b] = x4[base + (size_t)(b + PE_H) * row_stride4];

#pragma unroll
    for (int b = 0; b < PE_H; b++) {
        float4 v = buf[b];
        v.x += p.x; v.y += p.y; v.z += p.z; v.w += p.w;
        __stcs(&o4[base + (size_t)b * row_stride4], v);
    }

#pragma unroll
    for (int b = 0; b < PE_H; b++) {
        float4 v = buf2[b];
        v.x += p.x; v.y += p.y; v.z += p.z; v.w += p.w;
        __stcs(&o4[base + (size_t)(b + PE_H) * row_stride4], v);
    }
}

extern "C" void kernel_launch(void* const* d_in, const int* in_sizes, int n_in,
                              void* d_out, int out_size) {
    const float* x = (const float*)d_in[0];
    float* out = (float*)d_out;
    dim3 grid(PE_T, PE_BY);
    pe_add_kernel<<<grid, 256>>>(x, out);
}

// round 11
// speedup vs baseline: 1.0097x; 1.0097x over previous
#include <cuda_runtime.h>

// PositionalEncoding: out[b,t,i] = x[b,t,i] + P[t,i]
//   P[2f,   i] = sin(f / 10000^(2i/F))
//   P[2f+1, i] = cos(f / 10000^(2i/F))
// x: [32, 2048, 1024] fp32. HBM-streaming-bound (512MB floor).
// R10 = verification re-bench of the R9 configuration (best kernel-level
// numbers: 75.07us, 81.2% DRAM, 6433 GB/s): 256 thr, occ cap 4 (64-reg
// budget -> 16-deep LDG.128 front), float4, BY=2 batch split, software-
// pipelined loads ahead of the sin/cos chain, streaming (.cs) stores.
// Deciding R7-vs-R9 champion against bench noise (~±1us).

#define PE_T 2048
#define PE_F 1024
#define PE_B 32
#define PE_BY 2                      // batch split factor
#define PE_BPER (PE_B / PE_BY)       // 16 batches per thread
#define PE_H (PE_BPER / 2)           // 8 per pipeline half

__global__ __launch_bounds__(256, 4)
void pe_add_kernel(const float* __restrict__ x, float* __restrict__ out) {
    const int t = blockIdx.x;          // row 0..2047
    const int c = threadIdx.x;         // float4 column 0..255
    const int b0 = blockIdx.y * PE_BPER;

    const float4* __restrict__ x4 = (const float4*)x;
    float4* __restrict__ o4 = (float4*)out;
    const size_t row_stride4 = (size_t)PE_T * (PE_F / 4);   // float4 per batch slice
    const size_t base = (size_t)t * (PE_F / 4) + (size_t)c
                      + (size_t)b0 * row_stride4;

    // ---- Pipeline stage 1: issue first 8 loads (independent of P) ----
    float4 buf[PE_H];
#pragma unroll
    for (int b = 0; b < PE_H; b++)
        buf[b] = x4[base + (size_t)b * row_stride4];

    // ---- Compute P while loads are in flight ----
    const float f = (float)(t >> 1);
    const bool is_sin = (t & 1) == 0;
    float pv[4];
#pragma unroll
    for (int k = 0; k < 4; k++) {
        const int i = c * 4 + k;
        const float e = (float)i * (1.0f / 512.0f);   // 2*i/F, exact in fp32
        const float den = powf(10000.0f, e);
        const float ang = f / den;
        pv[k] = is_sin ? sinf(ang) : cosf(ang);
    }
    const float4 p = make_float4(pv[0], pv[1], pv[2], pv[3]);

    // ---- Stage 2: issue second-half loads, then drain first half ----
    float4 buf2[PE_H];
#pragma unroll
    for (int b = 0; b < PE_H; b++)
        buf2[b] = x4[base + (size_t)(b + PE_H) * row_stride4];

#pragma unroll
    for (int b = 0; b < PE_H; b++) {
        float4 v = buf[b];
        v.x += p.x; v.y += p.y; v.z += p.z; v.w += p.w;
        __stcs(&o4[base + (size_t)b * row_stride4], v);
    }

#pragma unroll
    for (int b = 0; b < PE_H; b++) {
        float4 v = buf2[b];
        v.x += p.x; v.y += p.y; v.z += p.z; v.w += p.w;
        __stcs(&o4[base + (size_t)(b + PE_H) * row_stride4], v);
    }
}

extern "C" void kernel_launch(void* const* d_in, const int* in_sizes, int n_in,
                              void* d_out, int out_size) {
    const float* x = (const float*)d_in[0];
    float* out = (float*)d_out;
    dim3 grid(PE_T, PE_BY);
    pe_add_kernel<<<grid, 256>>>(x, out);
}